// round 10
// baseline (speedup 1.0000x reference)
#include <cuda_runtime.h>
#include <cuda_bf16.h>
#include <cstdint>

// ---------------------------------------------------------------------------
// Problem constants
// ---------------------------------------------------------------------------
#define BATCH 8
#define CH    512
#define LEN   8192
#define PADL  8
#define LPAD  (LEN + 2*PADL)          // 8208
#define KTOT  3072                    // 3 taps * 512 ch * 2 halves
#define WELEM (512*512*3)             // 786432 elems per weight tensor

// conv tiling: BM=128, BN=128, 8 warps (256 thr), warp tile 64m x 32n
// 48 k-chunks of 64 (tap = kc>>4); 2 CTAs per SM (the point of this round)
#define BM 128
#define BN 128
#define NCHUNK 48
#define NSTG 2
#define ASTR 72                       // A smem row stride (bf16): 64 + 8 pad
#define BCOLS 144                     // B cols per row: [-8, 136) u32 (halo)
#define BSTR 168                      // B smem row stride (u32): ==8 mod 32
#define A_BYTES (128 * ASTR * 2)      // 18432
#define B_BYTES (32 * BSTR * 4)       // 21504
#define STAGE_BYTES (A_BYTES + B_BYTES)          // 39936
#define SMEM_TOTAL (NSTG * STAGE_BYTES)          // 79872  (x2 CTA = 160KB/SM)
#define NB16 (32 * (BCOLS / 4))       // cp.async.16 per B tile: 1152

// ---------------------------------------------------------------------------
// Scratch (device globals — no allocation allowed)
// ---------------------------------------------------------------------------
__device__ uint32_t       g_X2[(size_t)BATCH*CH*LPAD];   // split input  {hi,lo} u32
__device__ uint32_t       g_H2[(size_t)BATCH*CH*LPAD];   // split hidden {hi,lo} u32
__device__ __nv_bfloat16  g_Wq[(size_t)6*512*KTOT];      // ternary weights, k=(tap,c,half)
__device__ float          g_scales[6];

// ---------------------------------------------------------------------------
// Helpers
// ---------------------------------------------------------------------------
__device__ __forceinline__ uint32_t smem_u32(const void* p) {
    return (uint32_t)__cvta_generic_to_shared(p);
}
__device__ __forceinline__ uint32_t packsplit(float v) {
    __nv_bfloat16 h = __float2bfloat16(v);
    float r = v - __bfloat162float(h);
    __nv_bfloat16 lo = __float2bfloat16(r);
    return (uint32_t)__bfloat16_as_ushort(h) | ((uint32_t)__bfloat16_as_ushort(lo) << 16);
}
__device__ __forceinline__ void cp16(uint32_t dst, const void* src) {
    asm volatile("cp.async.cg.shared.global [%0], [%1], 16;\n" :: "r"(dst), "l"(src));
}
__device__ __forceinline__ void ldmA(uint32_t a[4], uint32_t addr) {
    asm volatile("ldmatrix.sync.aligned.m8n8.x4.shared.b16 {%0,%1,%2,%3}, [%4];\n"
                 : "=r"(a[0]), "=r"(a[1]), "=r"(a[2]), "=r"(a[3]) : "r"(addr));
}
__device__ __forceinline__ void mma16816(float c[4], const uint32_t a[4], const uint32_t b[2]) {
    asm volatile(
        "mma.sync.aligned.m16n8k16.row.col.f32.bf16.bf16.f32 "
        "{%0,%1,%2,%3}, {%4,%5,%6,%7}, {%8,%9}, {%0,%1,%2,%3};\n"
        : "+f"(c[0]), "+f"(c[1]), "+f"(c[2]), "+f"(c[3])
        : "r"(a[0]), "r"(a[1]), "r"(a[2]), "r"(a[3]), "r"(b[0]), "r"(b[1]));
}

// ---------------------------------------------------------------------------
// Weight prep: absmean scale (single launch, deterministic tree reduction)
// ---------------------------------------------------------------------------
__global__ void scales_all_kernel(const float* w0, const float* w1, const float* w2,
                                  const float* w3, const float* w4, const float* w5) {
    const float* ws[6] = {w0, w1, w2, w3, w4, w5};
    const float* w = ws[blockIdx.x];
    __shared__ float red[1024];
    float s = 0.f;
    for (int i = threadIdx.x; i < WELEM; i += 1024) s += fabsf(w[i]);
    red[threadIdx.x] = s;
    __syncthreads();
    for (int o = 512; o; o >>= 1) {
        if (threadIdx.x < o) red[threadIdx.x] += red[threadIdx.x + o];
        __syncthreads();
    }
    if (threadIdx.x == 0) g_scales[blockIdx.x] = red[0] / (float)WELEM + 1e-5f;
}

__global__ void quant_kernel(const float* w0, const float* w1, const float* w2,
                             const float* w3, const float* w4, const float* w5) {
    const float* ws[6] = {w0, w1, w2, w3, w4, w5};
    size_t idx = (size_t)blockIdx.x * 256 + threadIdx.x;
    if (idx >= (size_t)6 * WELEM) return;
    int widx = (int)(idx / WELEM);
    int rem  = (int)(idx % WELEM);
    int o    = rem / 1536;
    int r2   = rem % 1536;
    int tap  = r2 / 512;
    int cc   = r2 % 512;
    float scale = g_scales[widx];
    float v = ws[widx][((size_t)o * 512 + cc) * 3 + tap];
    float q = rintf(v / scale);                   // round-half-even, matches jnp.round
    q = fminf(1.f, fmaxf(-1.f, q));
    __nv_bfloat16 qb = __float2bfloat16(q);       // exact for {-1,0,1}
    size_t dst = (size_t)widx * 512 * KTOT + (size_t)o * KTOT + (size_t)tap * 1024 + cc * 2;
    g_Wq[dst]     = qb;                           // half 0 (hi)
    g_Wq[dst + 1] = qb;                           // half 1 (lo)
}

// ---------------------------------------------------------------------------
// Split fp32 -> {hi,lo} bf16 pair, into padded halo layout (+ optional copy to out)
// Also zeroes the g_H2 halo.  grid: (ceil(LPAD/256), BATCH*CH)
// ---------------------------------------------------------------------------
__global__ void split_kernel(const float* __restrict__ src, float* __restrict__ cpy) {
    int p = blockIdx.x * 256 + threadIdx.x;
    size_t bc = blockIdx.y;
    if (blockIdx.x == 0 && threadIdx.x < 16) {
        int j = threadIdx.x;                      // halo: 0..7 and 8200..8207
        g_H2[bc * LPAD + (j < 8 ? j : LEN + j)] = 0u;
    }
    if (p >= LPAD) return;
    int l = p - PADL;
    float v = 0.f;
    bool in = (l >= 0) && (l < LEN);
    if (in) v = src[bc * LEN + l];
    g_X2[bc * LPAD + p] = packsplit(v);
    if (cpy != nullptr && in) cpy[bc * LEN + l] = v;
}

// ---------------------------------------------------------------------------
// GEMM conv kernel.  SRCSEL: 0 reads g_X2, 1 reads g_H2.
// RESID=false: epilogue = scale+bias+LeakyReLU -> split-store into g_H2
// RESID=true : epilogue = scale+bias+residual  -> fp32 store into outF
// grid: (LEN/BN, CH/BM, BATCH), block 256, dynamic smem SMEM_TOTAL, 2 CTA/SM
// B tile loaded UNSHIFTED with +-8 u32 halo; dilation shift applied at LDS.
// ---------------------------------------------------------------------------
template <bool RESID, int SRCSEL>
__global__ __launch_bounds__(256, 2)
void conv_kernel(const float* __restrict__ bias, int widx, int dil,
                 float* __restrict__ outF) {
    extern __shared__ char smem[];

    const int lBase = blockIdx.x * BN;
    const int oBase = blockIdx.y * BM;
    const int bIdx  = blockIdx.z;
    const int tid   = threadIdx.x;
    const int lane  = tid & 31;
    const int wid   = tid >> 5;      // 0..7
    const int wm    = wid >> 2;      // 0..1  (64 m-rows each)
    const int wn    = wid & 3;       // 0..3  (32 n-cols each)
    const int g     = lane >> 2;     // 0..7
    const int tq    = lane & 3;      // 0..3

    const __nv_bfloat16* Aw = g_Wq + (size_t)widx * 512 * KTOT;
    const uint32_t* __restrict__ Bin = (SRCSEL == 0) ? g_X2 : g_H2;

    uint32_t  aB[NSTG];
    uint32_t  bB[NSTG];
    const uint32_t* bP[NSTG];
#pragma unroll
    for (int s = 0; s < NSTG; ++s) {
        char* stg = smem + s * STAGE_BYTES;
        aB[s] = smem_u32(stg);
        bB[s] = smem_u32(stg + A_BYTES);
        bP[s] = (const uint32_t*)(stg + A_BYTES);
    }

    float c[4][4][4];
#pragma unroll
    for (int mi = 0; mi < 4; ++mi)
#pragma unroll
        for (int ni = 0; ni < 4; ++ni)
#pragma unroll
            for (int r = 0; r < 4; ++r) c[mi][ni][r] = 0.f;

    auto loadStage = [&](int st, int kc) {
        // ---- A tile: 128 rows x 64 bf16 -> 4 cp16/thread (1024)
        {
            int q = tid * 4;
#pragma unroll
            for (int u = 0; u < 4; ++u, ++q) {
                int m   = q >> 3;                 // 0..127
                int kch = q & 7;                  // 8 bf16 groups
                cp16(aB[st] + (uint32_t)(m * ASTR + kch * 8) * 2,
                     Aw + (size_t)(oBase + m) * KTOT + kc * 64 + kch * 8);
            }
        }
        // ---- B tile: 32 channel rows x 144 u32 (cols [-8,136)) -> 1152 cp16
        {
            int cB = (kc & 15) << 5;              // 32 channels per chunk
            const uint32_t* srcBase =
                Bin + ((size_t)(bIdx * CH + cB)) * LPAD + (PADL + lBase - 8);
#pragma unroll
            for (int j = 0; j < 5; ++j) {
                int r = tid + 256 * j;
                if (r < NB16) {
                    int p = r / (BCOLS / 4);      // channel row 0..31
                    int q = r % (BCOLS / 4);      // 16B group 0..35
                    cp16(bB[st] + (uint32_t)(p * BSTR + q * 4) * 4,
                         srcBase + (size_t)p * LPAD + q * 4);
                }
            }
        }
    };

    auto mmaStage = [&](int st, int colOfs) {
        const uint32_t* Bsl = bP[st];
#pragma unroll
        for (int s = 0; s < 4; ++s) {             // 4 x k16 per 64-k chunk
            uint32_t afr[4][4];
#pragma unroll
            for (int mi = 0; mi < 4; ++mi) {
                uint32_t addr = aB[st] +
                    (uint32_t)(((wm * 64 + mi * 16 + (lane & 15)) * ASTR) +
                               s * 16 + ((lane >> 4) << 3)) * 2;
                ldmA(afr[mi], addr);
            }
            uint32_t bfr[4][2];
#pragma unroll
            for (int ni = 0; ni < 4; ++ni) {
                int col = colOfs + wn * 32 + ni * 8 + g;
                bfr[ni][0] = Bsl[(s * 8 + tq) * BSTR + col];
                bfr[ni][1] = Bsl[(s * 8 + 4 + tq) * BSTR + col];
            }
#pragma unroll
            for (int mi = 0; mi < 4; ++mi)
#pragma unroll
                for (int ni = 0; ni < 4; ++ni)
                    mma16816(c[mi][ni], afr[mi], bfr[ni]);
        }
    };

    // ---- pipeline: 2 stages, 48 chunks, one barrier per chunk
    loadStage(0, 0);
    asm volatile("cp.async.commit_group;\n" ::: "memory");

    for (int kc = 0; kc < NCHUNK; ++kc) {
        asm volatile("cp.async.wait_group 0;\n" ::: "memory");  // stage kc ready
        __syncthreads();                          // all warps done reading stage kc^1
        if (kc + 1 < NCHUNK) {
            loadStage((kc + 1) & 1, kc + 1);
            asm volatile("cp.async.commit_group;\n" ::: "memory");
        }
        int tap = kc >> 4;                        // 16 chunks per tap
        mmaStage(kc & 1, 8 + (tap - 1) * dil);
    }

    // ---- epilogue
    const float scale = g_scales[widx];
#pragma unroll
    for (int mi = 0; mi < 4; ++mi) {
        int o0 = oBase + wm * 64 + mi * 16 + g;
        float bv0 = bias[o0];
        float bv1 = bias[o0 + 8];
#pragma unroll
        for (int ni = 0; ni < 4; ++ni) {
            int l = lBase + wn * 32 + ni * 8 + tq * 2;
            float v0 = c[mi][ni][0] * scale + bv0;
            float v1 = c[mi][ni][1] * scale + bv0;
            float v2 = c[mi][ni][2] * scale + bv1;
            float v3 = c[mi][ni][3] * scale + bv1;
            if (RESID) {
                size_t i0 = ((size_t)(bIdx * CH + o0)) * LEN + l;
                size_t i1 = ((size_t)(bIdx * CH + o0 + 8)) * LEN + l;
                float2 r0 = *(const float2*)(outF + i0);
                float2 r1 = *(const float2*)(outF + i1);
                *(float2*)(outF + i0) = make_float2(v0 + r0.x, v1 + r0.y);
                *(float2*)(outF + i1) = make_float2(v2 + r1.x, v3 + r1.y);
            } else {
                v0 = (v0 >= 0.f) ? v0 : 0.1f * v0;
                v1 = (v1 >= 0.f) ? v1 : 0.1f * v1;
                v2 = (v2 >= 0.f) ? v2 : 0.1f * v2;
                v3 = (v3 >= 0.f) ? v3 : 0.1f * v3;
                size_t i0 = ((size_t)(bIdx * CH + o0)) * LPAD + PADL + l;
                size_t i1 = ((size_t)(bIdx * CH + o0 + 8)) * LPAD + PADL + l;
                *(uint2*)(&g_H2[i0]) = make_uint2(packsplit(v0), packsplit(v1));
                *(uint2*)(&g_H2[i1]) = make_uint2(packsplit(v2), packsplit(v3));
            }
        }
    }
}

// ---------------------------------------------------------------------------
// Launch.  ncu's fixed profiled slot is launch index 3 -> first conv kernel.
//   0: scales_all  1: quant  2: split  3: convA(branch0)  ...
// ---------------------------------------------------------------------------
extern "C" void kernel_launch(void* const* d_in, const int* in_sizes, int n_in,
                              void* d_out, int out_size) {
    const float* x = (const float*)d_in[0];
    const float* W[6];
    const float* Bv[6];
    for (int i = 0; i < 6; ++i) {
        W[i]  = (const float*)d_in[1 + 2 * i];
        Bv[i] = (const float*)d_in[2 + 2 * i];
    }
    float* out = (float*)d_out;

    // opt-in to >48KB dynamic smem (eager host-side call; idempotent, not captured)
    cudaFuncSetAttribute(conv_kernel<false, 0>,
                         cudaFuncAttributeMaxDynamicSharedMemorySize, SMEM_TOTAL);
    cudaFuncSetAttribute(conv_kernel<true, 1>,
                         cudaFuncAttributeMaxDynamicSharedMemorySize, SMEM_TOTAL);

    // weight prep (2 launches)
    scales_all_kernel<<<6, 1024>>>(W[0], W[1], W[2], W[3], W[4], W[5]);
    {
        size_t total = (size_t)6 * WELEM;
        int blocks = (int)((total + 255) / 256);
        quant_kernel<<<blocks, 256>>>(W[0], W[1], W[2], W[3], W[4], W[5]);
    }

    const dim3 cgrid(LEN / BN, CH / BM, BATCH);
    const dim3 sgrid((LPAD + 255) / 256, BATCH * CH);
    const int dils[3] = {1, 3, 5};

    for (int br = 0; br < 3; ++br) {
        // split current x (fp32) into hi/lo pairs; first branch also copies x -> out
        split_kernel<<<sgrid, 256>>>(br == 0 ? x : out, br == 0 ? out : nullptr);
        // conv A (dilated) + leaky + split-store -> g_H2
        conv_kernel<false, 0><<<cgrid, 256, SMEM_TOTAL>>>(Bv[2 * br], 2 * br, dils[br], nullptr);
        // conv B (dense) + bias + residual -> out
        conv_kernel<true, 1><<<cgrid, 256, SMEM_TOTAL>>>(Bv[2 * br + 1], 2 * br + 1, 1, out);
    }
}

// round 11
// speedup vs baseline: 2.0479x; 2.0479x over previous
#include <cuda_runtime.h>
#include <cuda_fp16.h>
#include <cstdint>

// ---------------------------------------------------------------------------
// Problem constants
// ---------------------------------------------------------------------------
#define BATCH 8
#define CH    512
#define CP    256                     // channel pairs
#define LEN   8192
#define PADL  8
#define LPAD  (LEN + 2*PADL)          // 8208
#define KTOT  1536                    // 3 taps * 512 ch  (single fp16, no hi/lo)
#define WELEM (512*512*3)             // 786432 elems per weight tensor

// conv tiling: BM=128, BN=256, 16 warps (512 thr), warp tile 64m x 32n
// 24 k-chunks of 64 (tap = kc>>3, 8 chunks of 64 channels per tap)
#define BM 128
#define BN 256
#define NCHUNK 24
#define NSTG 2
#define ASTR 72                       // A smem row stride (fp16): 64 + 8 pad
#define BCOLS 272                     // B cols per row: [-8, 264) u32 (halo)
#define BSTR 296                      // B smem row stride (u32): ==8 mod 32
#define A_BYTES (128 * ASTR * 2)      // 18432
#define B_BYTES (32 * BSTR * 4)       // 37888
#define STAGE_BYTES (A_BYTES + B_BYTES)          // 56320
#define SMEM_TOTAL (NSTG * STAGE_BYTES)          // 112640
#define NB16 (32 * (BCOLS / 4))       // cp.async.16 per B tile: 2176

// ---------------------------------------------------------------------------
// Scratch (device globals — no allocation allowed)
// Activations: u32 = {fp16 ch(2cp), fp16 ch(2cp+1)} indexed [b*CP+cp][pos]
// ---------------------------------------------------------------------------
__device__ uint32_t g_X2[(size_t)BATCH*CP*LPAD];
__device__ uint32_t g_H2[(size_t)BATCH*CP*LPAD];
__device__ __half   g_Wq[(size_t)6*512*KTOT];   // ternary weights [o][k=tap*512+c]
__device__ float    g_scales[6];

// ---------------------------------------------------------------------------
// Helpers
// ---------------------------------------------------------------------------
__device__ __forceinline__ uint32_t smem_u32(const void* p) {
    return (uint32_t)__cvta_generic_to_shared(p);
}
__device__ __forceinline__ uint32_t pack2h(float a, float b) {
    return (uint32_t)__half_as_ushort(__float2half_rn(a)) |
           ((uint32_t)__half_as_ushort(__float2half_rn(b)) << 16);
}
__device__ __forceinline__ void cp16(uint32_t dst, const void* src) {
    asm volatile("cp.async.cg.shared.global [%0], [%1], 16;\n" :: "r"(dst), "l"(src));
}
__device__ __forceinline__ void ldmA(uint32_t a[4], uint32_t addr) {
    asm volatile("ldmatrix.sync.aligned.m8n8.x4.shared.b16 {%0,%1,%2,%3}, [%4];\n"
                 : "=r"(a[0]), "=r"(a[1]), "=r"(a[2]), "=r"(a[3]) : "r"(addr));
}
__device__ __forceinline__ void mma16816(float c[4], const uint32_t a[4], const uint32_t b[2]) {
    asm volatile(
        "mma.sync.aligned.m16n8k16.row.col.f32.f16.f16.f32 "
        "{%0,%1,%2,%3}, {%4,%5,%6,%7}, {%8,%9}, {%0,%1,%2,%3};\n"
        : "+f"(c[0]), "+f"(c[1]), "+f"(c[2]), "+f"(c[3])
        : "r"(a[0]), "r"(a[1]), "r"(a[2]), "r"(a[3]), "r"(b[0]), "r"(b[1]));
}

// ---------------------------------------------------------------------------
// Weight prep: absmean scale + ternarize (fp16 exact for {-1,0,1})
// ---------------------------------------------------------------------------
__global__ void scales_all_kernel(const float* w0, const float* w1, const float* w2,
                                  const float* w3, const float* w4, const float* w5) {
    const float* ws[6] = {w0, w1, w2, w3, w4, w5};
    const float* w = ws[blockIdx.x];
    __shared__ float red[1024];
    float s = 0.f;
    for (int i = threadIdx.x; i < WELEM; i += 1024) s += fabsf(w[i]);
    red[threadIdx.x] = s;
    __syncthreads();
    for (int o = 512; o; o >>= 1) {
        if (threadIdx.x < o) red[threadIdx.x] += red[threadIdx.x + o];
        __syncthreads();
    }
    if (threadIdx.x == 0) g_scales[blockIdx.x] = red[0] / (float)WELEM + 1e-5f;
}

__global__ void quant_kernel(const float* w0, const float* w1, const float* w2,
                             const float* w3, const float* w4, const float* w5) {
    const float* ws[6] = {w0, w1, w2, w3, w4, w5};
    size_t idx = (size_t)blockIdx.x * 256 + threadIdx.x;
    if (idx >= (size_t)6 * WELEM) return;
    int widx = (int)(idx / WELEM);
    int rem  = (int)(idx % WELEM);
    int o    = rem / 1536;
    int r2   = rem % 1536;
    int tap  = r2 / 512;
    int cc   = r2 % 512;
    float scale = g_scales[widx];
    float v = ws[widx][((size_t)o * 512 + cc) * 3 + tap];
    float q = rintf(v / scale);                   // round-half-even, matches jnp.round
    q = fminf(1.f, fmaxf(-1.f, q));
    g_Wq[(size_t)widx * 512 * KTOT + (size_t)o * KTOT + tap * 512 + cc] = __float2half_rn(q);
}

// ---------------------------------------------------------------------------
// Split fp32 [c][pos] -> channel-pair fp16x2 u32 [cp][pos] with halo.
// Also zeroes the g_H2 halo; optional copy x -> out.
// grid: (ceil(LPAD/256), BATCH*CP)
// ---------------------------------------------------------------------------
__global__ void split_kernel(const float* __restrict__ src, float* __restrict__ cpy) {
    int p  = blockIdx.x * 256 + threadIdx.x;
    int b  = blockIdx.y >> 8;
    int cp = blockIdx.y & 255;
    size_t row = (size_t)b * CP + cp;
    if (blockIdx.x == 0 && threadIdx.x < 16) {
        int j = threadIdx.x;                      // halo: 0..7 and 8200..8207
        g_H2[row * LPAD + (j < 8 ? j : LEN + j)] = 0u;
    }
    if (p >= LPAD) return;
    int l = p - PADL;
    float v0 = 0.f, v1 = 0.f;
    bool in = (l >= 0) && (l < LEN);
    size_t s0 = ((size_t)(b * CH + 2 * cp)) * LEN + l;
    if (in) {
        v0 = src[s0];
        v1 = src[s0 + LEN];
    }
    g_X2[row * LPAD + p] = pack2h(v0, v1);
    if (cpy != nullptr && in) {
        cpy[s0] = v0;
        cpy[s0 + LEN] = v1;
    }
}

// ---------------------------------------------------------------------------
// GEMM conv kernel.  SRCSEL: 0 reads g_X2, 1 reads g_H2.
// RESID=false: epilogue = scale+bias+LeakyReLU -> fp16-pair store into g_H2
// RESID=true : epilogue = scale+bias+residual  -> fp32 store into outF
// grid: (LEN/BN, CH/BM, BATCH), block 512, dynamic smem SMEM_TOTAL
// B tile loaded UNSHIFTED with +-8 u32 halo; dilation shift applied at LDS.
// ---------------------------------------------------------------------------
template <bool RESID, int SRCSEL>
__global__ __launch_bounds__(512, 1)
void conv_kernel(const float* __restrict__ bias, int widx, int dil,
                 float* __restrict__ outF) {
    extern __shared__ char smem[];

    const int lBase = blockIdx.x * BN;
    const int oBase = blockIdx.y * BM;
    const int bIdx  = blockIdx.z;
    const int tid   = threadIdx.x;
    const int lane  = tid & 31;
    const int wid   = tid >> 5;      // 0..15
    const int wm    = wid >> 3;      // 0..1  (64 m-rows each)
    const int wn    = wid & 7;       // 0..7  (32 n-cols each)
    const int g     = lane >> 2;     // 0..7
    const int tq    = lane & 3;      // 0..3

    const __half* Aw = g_Wq + (size_t)widx * 512 * KTOT;
    const uint32_t* __restrict__ Bin = (SRCSEL == 0) ? g_X2 : g_H2;

    uint32_t  aB[NSTG];
    uint32_t  bB[NSTG];
    const uint32_t* bP[NSTG];
#pragma unroll
    for (int s = 0; s < NSTG; ++s) {
        char* stg = smem + s * STAGE_BYTES;
        aB[s] = smem_u32(stg);
        bB[s] = smem_u32(stg + A_BYTES);
        bP[s] = (const uint32_t*)(stg + A_BYTES);
    }

    float c[4][4][4];
#pragma unroll
    for (int mi = 0; mi < 4; ++mi)
#pragma unroll
        for (int ni = 0; ni < 4; ++ni)
#pragma unroll
            for (int r = 0; r < 4; ++r) c[mi][ni][r] = 0.f;

    auto loadStage = [&](int st, int kc) {
        // ---- A tile: 128 rows x 64 fp16 -> 2 cp16/thread (1024)
        {
            int q = tid * 2;
#pragma unroll
            for (int u = 0; u < 2; ++u, ++q) {
                int m   = q >> 3;                 // 0..127
                int kch = q & 7;                  // 8 fp16 groups
                cp16(aB[st] + (uint32_t)(m * ASTR + kch * 8) * 2,
                     Aw + (size_t)(oBase + m) * KTOT + kc * 64 + kch * 8);
            }
        }
        // ---- B tile: 32 cp-rows x 272 u32 (cols [-8,264)) -> 2176 cp16
        {
            int cB = (kc & 7) << 5;               // 32 channel-pairs per chunk
            const uint32_t* srcBase =
                Bin + ((size_t)(bIdx * CP + cB)) * LPAD + (PADL + lBase - 8);
#pragma unroll
            for (int j = 0; j < 5; ++j) {
                int r = tid + 512 * j;
                if (r < NB16) {
                    int p = r / (BCOLS / 4);      // cp-row 0..31
                    int q = r % (BCOLS / 4);      // 16B group 0..67
                    cp16(bB[st] + (uint32_t)(p * BSTR + q * 4) * 4,
                         srcBase + (size_t)p * LPAD + q * 4);
                }
            }
        }
    };

    auto mmaStage = [&](int st, int colOfs) {
        const uint32_t* Bsl = bP[st];
#pragma unroll
        for (int s = 0; s < 4; ++s) {             // 4 x k16 per 64-k chunk
            uint32_t afr[4][4];
#pragma unroll
            for (int mi = 0; mi < 4; ++mi) {
                uint32_t addr = aB[st] +
                    (uint32_t)(((wm * 64 + mi * 16 + (lane & 15)) * ASTR) +
                               s * 16 + ((lane >> 4) << 3)) * 2;
                ldmA(afr[mi], addr);
            }
            uint32_t bfr[4][2];
#pragma unroll
            for (int ni = 0; ni < 4; ++ni) {
                int col = colOfs + wn * 32 + ni * 8 + g;
                bfr[ni][0] = Bsl[(s * 8 + tq) * BSTR + col];
                bfr[ni][1] = Bsl[(s * 8 + 4 + tq) * BSTR + col];
            }
#pragma unroll
            for (int mi = 0; mi < 4; ++mi)
#pragma unroll
                for (int ni = 0; ni < 4; ++ni)
                    mma16816(c[mi][ni], afr[mi], bfr[ni]);
        }
    };

    // ---- pipeline: 2 stages, 24 chunks, one barrier per chunk
    loadStage(0, 0);
    asm volatile("cp.async.commit_group;\n" ::: "memory");

    for (int kc = 0; kc < NCHUNK; ++kc) {
        asm volatile("cp.async.wait_group 0;\n" ::: "memory");  // stage kc ready
        __syncthreads();                          // all warps done reading stage kc^1
        if (kc + 1 < NCHUNK) {
            loadStage((kc + 1) & 1, kc + 1);
            asm volatile("cp.async.commit_group;\n" ::: "memory");
        }
        int tap = kc >> 3;                        // 8 chunks per tap
        mmaStage(kc & 1, 8 + (tap - 1) * dil);
    }

    // ---- epilogue
    const float scale = g_scales[widx];
#pragma unroll
    for (int mi = 0; mi < 4; ++mi) {
        int o0 = oBase + wm * 64 + mi * 16 + g;
        float bv0 = bias[o0];
        float bv1 = bias[o0 + 8];
#pragma unroll
        for (int ni = 0; ni < 4; ++ni) {
            int l = lBase + wn * 32 + ni * 8 + tq * 2;
            float v0 = c[mi][ni][0] * scale + bv0;
            float v1 = c[mi][ni][1] * scale + bv0;
            float v2 = c[mi][ni][2] * scale + bv1;
            float v3 = c[mi][ni][3] * scale + bv1;
            if (RESID) {
                size_t i0 = ((size_t)(bIdx * CH + o0)) * LEN + l;
                size_t i1 = ((size_t)(bIdx * CH + o0 + 8)) * LEN + l;
                float2 r0 = *(const float2*)(outF + i0);
                float2 r1 = *(const float2*)(outF + i1);
                *(float2*)(outF + i0) = make_float2(v0 + r0.x, v1 + r0.y);
                *(float2*)(outF + i1) = make_float2(v2 + r1.x, v3 + r1.y);
            } else {
                v0 = (v0 >= 0.f) ? v0 : 0.1f * v0;
                v1 = (v1 >= 0.f) ? v1 : 0.1f * v1;
                v2 = (v2 >= 0.f) ? v2 : 0.1f * v2;
                v3 = (v3 >= 0.f) ? v3 : 0.1f * v3;
                // pair adjacent channels: lane g holds row o0, lane g^1 holds o0^1
                float p0 = __shfl_xor_sync(0xffffffffu, v0, 4);
                float p1 = __shfl_xor_sync(0xffffffffu, v1, 4);
                float p2 = __shfl_xor_sync(0xffffffffu, v2, 4);
                float p3 = __shfl_xor_sync(0xffffffffu, v3, 4);
                if ((g & 1) == 0) {               // even channel lanes store pairs
                    int cp0 = o0 >> 1;            // rows o0,o0+1
                    int cp1 = cp0 + 4;            // rows o0+8,o0+9
                    size_t r0i = ((size_t)(bIdx * CP + cp0)) * LPAD + PADL + l;
                    size_t r1i = ((size_t)(bIdx * CP + cp1)) * LPAD + PADL + l;
                    *(uint2*)(&g_H2[r0i]) = make_uint2(pack2h(v0, p0), pack2h(v1, p1));
                    *(uint2*)(&g_H2[r1i]) = make_uint2(pack2h(v2, p2), pack2h(v3, p3));
                }
            }
        }
    }
}

// ---------------------------------------------------------------------------
// Launch.  ncu's fixed profiled slot is launch index 3 -> first conv kernel.
//   0: scales_all  1: quant  2: split  3: convA(branch0)  ...
// ---------------------------------------------------------------------------
extern "C" void kernel_launch(void* const* d_in, const int* in_sizes, int n_in,
                              void* d_out, int out_size) {
    const float* x = (const float*)d_in[0];
    const float* W[6];
    const float* Bv[6];
    for (int i = 0; i < 6; ++i) {
        W[i]  = (const float*)d_in[1 + 2 * i];
        Bv[i] = (const float*)d_in[2 + 2 * i];
    }
    float* out = (float*)d_out;

    // opt-in to >48KB dynamic smem (eager host-side call; idempotent, not captured)
    cudaFuncSetAttribute(conv_kernel<false, 0>,
                         cudaFuncAttributeMaxDynamicSharedMemorySize, SMEM_TOTAL);
    cudaFuncSetAttribute(conv_kernel<true, 1>,
                         cudaFuncAttributeMaxDynamicSharedMemorySize, SMEM_TOTAL);

    // weight prep (2 launches)
    scales_all_kernel<<<6, 1024>>>(W[0], W[1], W[2], W[3], W[4], W[5]);
    {
        size_t total = (size_t)6 * WELEM;
        int blocks = (int)((total + 255) / 256);
        quant_kernel<<<blocks, 256>>>(W[0], W[1], W[2], W[3], W[4], W[5]);
    }

    const dim3 cgrid(LEN / BN, CH / BM, BATCH);
    const dim3 sgrid((LPAD + 255) / 256, BATCH * CP);
    const int dils[3] = {1, 3, 5};

    for (int br = 0; br < 3; ++br) {
        // split current x (fp32) into fp16 channel pairs; first branch copies x -> out
        split_kernel<<<sgrid, 256>>>(br == 0 ? x : out, br == 0 ? out : nullptr);
        // conv A (dilated) + leaky -> g_H2
        conv_kernel<false, 0><<<cgrid, 512, SMEM_TOTAL>>>(Bv[2 * br], 2 * br, dils[br], nullptr);
        // conv B (dense) + bias + residual -> out
        conv_kernel<true, 1><<<cgrid, 512, SMEM_TOTAL>>>(Bv[2 * br + 1], 2 * br + 1, 1, out);
    }
}